// round 16
// baseline (speedup 1.0000x reference)
#include <cuda_runtime.h>
#include <math.h>
#include <float.h>
#include <stdint.h>

// Problem constants (fixed: x[2048,512], memories[8192,512], k=5, beta=1, steps=2)
#define BQ 2048
#define NM 8192
#define DD 512
#define NCOL 5
#define MR (NCOL * BQ)          // 10240 batched z rows
#define BISECT_ITERS 64
#define CAP 1024                // per-row sparse support cap
#define MARGIN 300.0f           // score-margin for provable one-hot collapse

// ---------------- scratch (device globals; no runtime allocation) ----------------
__device__ float g_L[(size_t)MR * NM];
__device__ float g_Z[(size_t)MR * DD];
__device__ int   g_cidx[(size_t)BQ * CAP];
__device__ float g_cw[(size_t)NCOL * BQ * CAP];
__device__ int   g_ccnt[BQ];
__device__ float g_m2[NM];
__device__ float g_x2[BQ];
__device__ float g_zn2c[MR];
__device__ int   g_amap1[MR];
__device__ int   g_amap2[MR];
__device__ int   g_cnt1;
__device__ int   g_cnt2;

__device__ __forceinline__ float sigmoidf_(float t) { return 1.0f / (1.0f + __expf(-t)); }

__device__ __forceinline__ void top2_merge(float& s1, int& i1, float& s2,
                                           float os1, int oi1, float os2) {
    if (os1 > s1) { s2 = fmaxf(s1, os2); s1 = os1; i1 = oi1; }
    else          { s2 = fmaxf(s2, os1); }
}

// descending compare-exchange with index tie-break
__device__ __forceinline__ void ce6(float* v, int* ix, int a, int b) {
    bool sw = (v[a] < v[b]) || (v[a] == v[b] && ix[a] > ix[b]);
    if (sw) {
        float tv = v[a]; v[a] = v[b]; v[b] = tv;
        int   ti = ix[a]; ix[a] = ix[b]; ix[b] = ti;
    }
}
__device__ __forceinline__ void sort6(float* v, int* ix) {
    ce6(v, ix, 0, 5); ce6(v, ix, 1, 3); ce6(v, ix, 2, 4);
    ce6(v, ix, 1, 2); ce6(v, ix, 3, 4);
    ce6(v, ix, 0, 3); ce6(v, ix, 2, 5);
    ce6(v, ix, 0, 1); ce6(v, ix, 2, 3); ce6(v, ix, 4, 5);
    ce6(v, ix, 1, 2); ce6(v, ix, 3, 4);
}
__device__ __forceinline__ void ins6(float val, int idx, float* v, int* ix) {
    if (val > v[5] || (val == v[5] && idx < ix[5])) {
        v[5] = val; ix[5] = idx;
#pragma unroll
        for (int j = 5; j > 0; j--) ce6(v, ix, j - 1, j);
    }
}

// ---------------- clear lists/counters ----------------
__global__ void clear_kernel(int* amap1, int* amap2, int* cnt1, int* cnt2)
{
    int i = blockIdx.x * blockDim.x + threadIdx.x;
    if (i < MR) { amap1[i] = 0; amap2[i] = 0; }
    if (i == 0) { *cnt1 = 0; *cnt2 = 0; }
}

// ---------------- row squared-norms (direct) ----------------
__global__ void rownorm2_kernel(const float* __restrict__ A, float* __restrict__ out, int cols)
{
    int r = blockIdx.x;
    const float* a = A + (size_t)r * cols;
    float s = 0.f;
    for (int c = threadIdx.x; c < cols; c += blockDim.x) { float v = a[c]; s = fmaf(v, v, s); }
#pragma unroll
    for (int o = 16; o; o >>= 1) s += __shfl_xor_sync(0xffffffffu, s, o);
    __shared__ float red[4];
    if ((threadIdx.x & 31) == 0) red[threadIdx.x >> 5] = s;
    __syncthreads();
    if (threadIdx.x == 0) out[r] = red[0] + red[1] + red[2] + red[3];
}

// ================= 256x128 tile GEMM machinery (16x8 per thread) =================
// As[16][256], Bs[16][128]; per-thread per kk: 4 A-frag LDS.128 + 2 B-frag LDS.128
// for 128 FMAs -> 0.75 B/FMA (crossbar below FFMA pipe).

__device__ __forceinline__ void mm_stage256(const float (*As)[256], const float (*Bs)[128],
                                            float acc[16][8], int ty, int tx)
{
#pragma unroll
    for (int kk = 0; kk < 16; kk++) {
        float a[16], b[8];
        float4 a0 = *(const float4*)&As[kk][ty * 16];
        float4 a1 = *(const float4*)&As[kk][ty * 16 + 4];
        float4 a2 = *(const float4*)&As[kk][ty * 16 + 8];
        float4 a3 = *(const float4*)&As[kk][ty * 16 + 12];
        float4 b0 = *(const float4*)&Bs[kk][tx * 8];
        float4 b1 = *(const float4*)&Bs[kk][tx * 8 + 4];
        a[0]=a0.x; a[1]=a0.y; a[2]=a0.z; a[3]=a0.w; a[4]=a1.x; a[5]=a1.y; a[6]=a1.z; a[7]=a1.w;
        a[8]=a2.x; a[9]=a2.y; a[10]=a2.z; a[11]=a2.w; a[12]=a3.x; a[13]=a3.y; a[14]=a3.z; a[15]=a3.w;
        b[0]=b0.x; b[1]=b0.y; b[2]=b0.z; b[3]=b0.w; b[4]=b1.x; b[5]=b1.y; b[6]=b1.z; b[7]=b1.w;
#pragma unroll
        for (int i = 0; i < 16; i++)
#pragma unroll
            for (int j = 0; j < 8; j++) acc[i][j] = fmaf(a[i], b[j], acc[i][j]);
    }
}

__device__ __forceinline__ void mm_store256(float (*As)[256], float (*Bs)[128], int lr, int lc,
                                            const float4 ra[4], const float4 rb[2])
{
#pragma unroll
    for (int q = 0; q < 4; q++) {
        int r = lr + q * 64;
        As[lc + 0][r] = ra[q].x; As[lc + 1][r] = ra[q].y;
        As[lc + 2][r] = ra[q].z; As[lc + 3][r] = ra[q].w;
    }
#pragma unroll
    for (int q = 0; q < 2; q++) {
        int r = lr + q * 64;
        Bs[lc + 0][r] = rb[q].x; Bs[lc + 1][r] = rb[q].y;
        Bs[lc + 2][r] = rb[q].z; Bs[lc + 3][r] = rb[q].w;
    }
}

// ---------------- NT SGEMM (256x128, double-buffered) with distance epilogue, direct A ----------------
__global__ void __launch_bounds__(256, 1)
sgemm_nt_ep(const float* __restrict__ A, const float* __restrict__ Bm,
            const float* __restrict__ arow, const float* __restrict__ bcol,
            float* __restrict__ C, int M, int N, int K)
{
    __shared__ float As[2][16][256];
    __shared__ float Bs[2][16][128];
    const int bm = blockIdx.y * 256;
    const int bn = blockIdx.x * 128;
    const int tid = threadIdx.x;
    const int tx = tid & 15;
    const int ty = tid >> 4;
    const int lr = tid >> 2;
    const int lc = (tid & 3) << 2;

    const float* pa[4];
#pragma unroll
    for (int q = 0; q < 4; q++) pa[q] = A + (size_t)(bm + lr + q * 64) * K + lc;
    const float* pb[2];
#pragma unroll
    for (int q = 0; q < 2; q++) pb[q] = Bm + (size_t)(bn + lr + q * 64) * K + lc;

    float acc[16][8];
#pragma unroll
    for (int i = 0; i < 16; i++)
#pragma unroll
        for (int j = 0; j < 8; j++) acc[i][j] = 0.f;

    const int NS = K >> 4;
    float4 ra[4], rb[2];
#pragma unroll
    for (int q = 0; q < 4; q++) ra[q] = *(const float4*)pa[q];
#pragma unroll
    for (int q = 0; q < 2; q++) rb[q] = *(const float4*)pb[q];
    mm_store256(As[0], Bs[0], lr, lc, ra, rb);
    __syncthreads();

    for (int s = 0; s < NS; s++) {
        if (s + 1 < NS) {
            int k0 = (s + 1) << 4;
#pragma unroll
            for (int q = 0; q < 4; q++) ra[q] = *(const float4*)(pa[q] + k0);
#pragma unroll
            for (int q = 0; q < 2; q++) rb[q] = *(const float4*)(pb[q] + k0);
        }
        mm_stage256(As[s & 1], Bs[s & 1], acc, ty, tx);
        if (s + 1 < NS) {
            mm_store256(As[(s + 1) & 1], Bs[(s + 1) & 1], lr, lc, ra, rb);
            __syncthreads();
        }
    }

#pragma unroll
    for (int i = 0; i < 16; i++) {
        int gr = bm + ty * 16 + i;
        float ar = arow[gr];
#pragma unroll
        for (int j = 0; j < 8; j += 4) {
            int gc = bn + tx * 8 + j;
            float4 o;
            o.x = -fmaxf((ar + bcol[gc + 0]) - 2.f * acc[i][j + 0], 0.f);
            o.y = -fmaxf((ar + bcol[gc + 1]) - 2.f * acc[i][j + 1], 0.f);
            o.z = -fmaxf((ar + bcol[gc + 2]) - 2.f * acc[i][j + 2], 0.f);
            o.w = -fmaxf((ar + bcol[gc + 3]) - 2.f * acc[i][j + 3], 0.f);
            *(float4*)(C + (size_t)gr * N + gc) = o;
        }
    }
}

// ---------------- NT SGEMM, indirect A rows (256x128, double-buffered) ----------------
__global__ void __launch_bounds__(256, 1)
sgemm_nt_ep_ind(const float* __restrict__ Z, const int* __restrict__ amap,
                const int* __restrict__ ncnt, const float* __restrict__ Bm,
                const float* __restrict__ arow, const float* __restrict__ bcol,
                float* __restrict__ C)
{
    const int bm = blockIdx.y * 256;
    if (bm >= *ncnt) return;
    __shared__ float As[2][16][256];
    __shared__ float Bs[2][16][128];
    const int bn = blockIdx.x * 128;
    const int tid = threadIdx.x;
    const int tx = tid & 15;
    const int ty = tid >> 4;
    const int lr = tid >> 2;
    const int lc = (tid & 3) << 2;

    const float* pa[4];
#pragma unroll
    for (int q = 0; q < 4; q++) pa[q] = Z + (size_t)amap[bm + lr + q * 64] * DD + lc;
    const float* pb[2];
#pragma unroll
    for (int q = 0; q < 2; q++) pb[q] = Bm + (size_t)(bn + lr + q * 64) * DD + lc;

    float acc[16][8];
#pragma unroll
    for (int i = 0; i < 16; i++)
#pragma unroll
        for (int j = 0; j < 8; j++) acc[i][j] = 0.f;

    const int NS = DD >> 4;   // 32
    float4 ra[4], rb[2];
#pragma unroll
    for (int q = 0; q < 4; q++) ra[q] = *(const float4*)pa[q];
#pragma unroll
    for (int q = 0; q < 2; q++) rb[q] = *(const float4*)pb[q];
    mm_store256(As[0], Bs[0], lr, lc, ra, rb);
    __syncthreads();

    for (int s = 0; s < NS; s++) {
        if (s + 1 < NS) {
            int k0 = (s + 1) << 4;
#pragma unroll
            for (int q = 0; q < 4; q++) ra[q] = *(const float4*)(pa[q] + k0);
#pragma unroll
            for (int q = 0; q < 2; q++) rb[q] = *(const float4*)(pb[q] + k0);
        }
        mm_stage256(As[s & 1], Bs[s & 1], acc, ty, tx);
        if (s + 1 < NS) {
            mm_store256(As[(s + 1) & 1], Bs[(s + 1) & 1], lr, lc, ra, rb);
            __syncthreads();
        }
    }

#pragma unroll
    for (int i = 0; i < 16; i++) {
        int gr = bm + ty * 16 + i;
        float ar = arow[gr];
#pragma unroll
        for (int j = 0; j < 8; j += 4) {
            int gc = bn + tx * 8 + j;
            float4 o;
            o.x = -fmaxf((ar + bcol[gc + 0]) - 2.f * acc[i][j + 0], 0.f);
            o.y = -fmaxf((ar + bcol[gc + 1]) - 2.f * acc[i][j + 1], 0.f);
            o.z = -fmaxf((ar + bcol[gc + 2]) - 2.f * acc[i][j + 2], 0.f);
            o.w = -fmaxf((ar + bcol[gc + 3]) - 2.f * acc[i][j + 3], 0.f);
            *(float4*)(C + (size_t)gr * NM + gc) = o;
        }
    }
}

// ---------------- stats + LML + sparse plane extraction (one block per x-row) ----------------
__global__ void __launch_bounds__(256)
stats_planes_kernel(const float* __restrict__ X, int* __restrict__ cidx,
                    float* __restrict__ cw, int* __restrict__ ccnt)
{
    __shared__ float s_row[NM];
    __shared__ float s_cand[CAP];
    __shared__ int   s_ci[CAP];
    __shared__ float s_redf[8];
    __shared__ float s_t6v[8][6];
    __shared__ int   s_t6i[8][6];
    __shared__ float s_topv[6];
    __shared__ int   s_wcnt[8];
    __shared__ int   s_base;
    __shared__ float s_max, s_sum;
    __shared__ float s_nu[4];

    const int b = blockIdx.x;
    const int tid = threadIdx.x, lane = tid & 31, w = tid >> 5;
    const float4* x4 = (const float4*)(X + (size_t)b * NM);

    float lm[4] = {-FLT_MAX, -FLT_MAX, -FLT_MAX, -FLT_MAX};
#pragma unroll
    for (int u = 0; u < 8; u++) {
        int i = tid + u * 256;
        float4 v = x4[i];
        ((float4*)s_row)[i] = v;
        lm[u & 3] = fmaxf(lm[u & 3], fmaxf(fmaxf(v.x, v.y), fmaxf(v.z, v.w)));
    }
    float lmax = fmaxf(fmaxf(lm[0], lm[1]), fmaxf(lm[2], lm[3]));
#pragma unroll
    for (int o = 16; o; o >>= 1) lmax = fmaxf(lmax, __shfl_xor_sync(0xffffffffu, lmax, o));
    if (lane == 0) s_redf[w] = lmax;
    __syncthreads();
    if (tid == 0) {
        float m = s_redf[0];
        for (int i = 1; i < 8; i++) m = fmaxf(m, s_redf[i]);
        s_max = m;
    }
    __syncthreads();
    const float rmax = s_max;

    float ls = 0.f;
    for (int i = tid; i < NM; i += 256) ls += __expf(s_row[i] - rmax);
#pragma unroll
    for (int o = 16; o; o >>= 1) ls += __shfl_xor_sync(0xffffffffu, ls, o);
    __syncthreads();
    if (lane == 0) s_redf[w] = ls;
    __syncthreads();
    if (tid == 0) {
        float t = 0.f;
        for (int i = 0; i < 8; i++) t += s_redf[i];
        s_sum = t;
    }

    // single-pass top-6
    float tv[6]; int ti[6];
#pragma unroll
    for (int j = 0; j < 6; j++) { tv[j] = -FLT_MAX; ti[j] = 0x7fffffff; }
    for (int i = tid; i < NM; i += 256) ins6(s_row[i], i, tv, ti);
#pragma unroll
    for (int o = 16; o; o >>= 1) {
        float ov[6]; int oi[6];
#pragma unroll
        for (int j = 0; j < 6; j++) {
            ov[j] = __shfl_xor_sync(0xffffffffu, tv[j], o);
            oi[j] = __shfl_xor_sync(0xffffffffu, ti[j], o);
        }
        float nv[6]; int ni[6];
#pragma unroll
        for (int q = 0; q < 6; q++) {
            bool ta = (tv[q] > ov[5 - q]) || (tv[q] == ov[5 - q] && ti[q] <= oi[5 - q]);
            nv[q] = ta ? tv[q] : ov[5 - q];
            ni[q] = ta ? ti[q] : oi[5 - q];
        }
#pragma unroll
        for (int j = 0; j < 6; j++) { tv[j] = nv[j]; ti[j] = ni[j]; }
        sort6(tv, ti);
    }
    if (lane == 0) {
#pragma unroll
        for (int j = 0; j < 6; j++) { s_t6v[w][j] = tv[j]; s_t6i[w][j] = ti[j]; }
    }
    __syncthreads();
    if (tid == 0) {
        float fv[6]; int fi[6];
#pragma unroll
        for (int j = 0; j < 6; j++) { fv[j] = s_t6v[0][j]; fi[j] = s_t6i[0][j]; }
        for (int q = 1; q < 8; q++)
            for (int j = 0; j < 6; j++) ins6(s_t6v[q][j], s_t6i[q][j], fv, fi);
#pragma unroll
        for (int j = 0; j < 6; j++) s_topv[j] = fv[j];
        s_base = 0;
    }
    __syncthreads();

    const float thr = s_topv[5] - 34.0f;
    for (int i0 = 0; i0 < NM; i0 += 256) {
        int i = i0 + tid;
        float v = s_row[i];
        bool p = (v > thr);
        unsigned mk = __ballot_sync(0xffffffffu, p);
        if (lane == 0) s_wcnt[w] = __popc(mk);
        __syncthreads();
        int woff = 0, tot = 0;
#pragma unroll
        for (int q = 0; q < 8; q++) { if (q < w) woff += s_wcnt[q]; tot += s_wcnt[q]; }
        int pos = s_base + woff + __popc(mk & ((1u << lane) - 1u));
        if (p && pos < CAP) { s_cand[pos] = v; s_ci[pos] = i; }
        __syncthreads();
        if (tid == 0) s_base = min(s_base + tot, CAP);
        __syncthreads();
    }
    const int total = s_base;

    if (w < 4) {
        const int kk = w + 2;
        float lo = -s_topv[kk - 1] - 7.0f;
        float hi = -s_topv[kk] + 7.0f;
        for (int it = 0; it < BISECT_ITERS; it++) {
            float mid = 0.5f * (lo + hi);
            float s = 0.f;
            for (int c = lane; c < total; c += 32) s += sigmoidf_(s_cand[c] + mid);
#pragma unroll
            for (int o = 16; o; o >>= 1) s += __shfl_xor_sync(0xffffffffu, s, o);
            if (s - (float)kk < 0.f) lo = mid; else hi = mid;
        }
        if (lane == 0) s_nu[kk - 2] = 0.5f * (lo + hi);
    }
    __syncthreads();

    const float ssum = s_sum;
    const float nu2 = s_nu[0], nu3 = s_nu[1], nu4 = s_nu[2], nu5 = s_nu[3];
    const size_t PL = (size_t)BQ * CAP;
    for (int c = tid; c < total; c += 256) {
        float xv = s_cand[c];
        float p  = __expf(xv - rmax) / ssum;
        float y2 = sigmoidf_(xv + nu2);
        float y3 = sigmoidf_(xv + nu3);
        float y4 = sigmoidf_(xv + nu4);
        float y5 = sigmoidf_(xv + nu5);
        size_t o = (size_t)b * CAP + c;
        cidx[o] = s_ci[c];
        cw[o]          = p;
        cw[PL + o]     = y2 - p;
        cw[2 * PL + o] = y3 - y2;
        cw[3 * PL + o] = y4 - y3;
        cw[4 * PL + o] = y5 - y4;
    }
    if (tid == 0) ccnt[b] = total;
}

// ---------------- init activity: margin-converged rows skip hopfield; norm fused ----------------
__global__ void __launch_bounds__(128)
init_activity_kernel(const float* __restrict__ Xi, const float* __restrict__ m2,
                     const int* __restrict__ cidx, const float* __restrict__ cw,
                     const int* __restrict__ ccnt, float* __restrict__ Z,
                     int* __restrict__ amap1, int* __restrict__ cnt1,
                     float* __restrict__ zn2c)
{
    __shared__ float s_s1[4], s_s2[4];
    __shared__ int   s_i1[4];
    __shared__ float r_s1, r_s2;
    __shared__ int   r_i1;
    __shared__ float s_nred[4];

    const int r = blockIdx.x;
    const int k = r >> 11, b = r & 2047;
    const int n = ccnt[b];
    const int* id = cidx + (size_t)b * CAP;
    const float* wp = cw + (size_t)k * ((size_t)BQ * CAP) + (size_t)b * CAP;
    const int t = threadIdx.x, lane = t & 31, w = t >> 5;

    float s1 = -FLT_MAX, s2 = -FLT_MAX; int i1 = 0;
    for (int c = t; c < n; c += 128) {
        float sc = (2.f * wp[c] - 1.f) * m2[id[c]];
        top2_merge(s1, i1, s2, sc, id[c], -FLT_MAX);
    }
#pragma unroll
    for (int o = 16; o; o >>= 1) {
        float os1 = __shfl_xor_sync(0xffffffffu, s1, o);
        int   oi1 = __shfl_xor_sync(0xffffffffu, i1, o);
        float os2 = __shfl_xor_sync(0xffffffffu, s2, o);
        top2_merge(s1, i1, s2, os1, oi1, os2);
    }
    if (lane == 0) { s_s1[w] = s1; s_i1[w] = i1; s_s2[w] = s2; }
    __syncthreads();
    if (t == 0) {
        float a1 = s_s1[0], a2 = s_s2[0]; int ai = s_i1[0];
        for (int i = 1; i < 4; i++) top2_merge(a1, ai, a2, s_s1[i], s_i1[i], s_s2[i]);
        r_s1 = a1; r_s2 = a2; r_i1 = ai;
    }
    __syncthreads();

    if (r_s1 > 0.f && r_s1 - r_s2 > MARGIN) {
        float4 v = ((const float4*)(Xi + (size_t)r_i1 * DD))[t];
        ((float4*)(Z + (size_t)r * DD))[t] = v;
    } else {
        float4 acc = make_float4(0.f, 0.f, 0.f, 0.f);
        for (int c = 0; c < n; c++) {
            float wv = wp[c];
            float4 v = ((const float4*)(Xi + (size_t)id[c] * DD))[t];
            acc.x = fmaf(wv, v.x, acc.x); acc.y = fmaf(wv, v.y, acc.y);
            acc.z = fmaf(wv, v.z, acc.z); acc.w = fmaf(wv, v.w, acc.w);
        }
        ((float4*)(Z + (size_t)r * DD))[t] = acc;
        float nr = acc.x * acc.x;
        nr = fmaf(acc.y, acc.y, nr);
        nr = fmaf(acc.z, acc.z, nr);
        nr = fmaf(acc.w, acc.w, nr);
#pragma unroll
        for (int o = 16; o; o >>= 1) nr += __shfl_xor_sync(0xffffffffu, nr, o);
        if (lane == 0) s_nred[w] = nr;
        __syncthreads();
        if (t == 0) {
            float nm = s_nred[0] + s_nred[1] + s_nred[2] + s_nred[3];
            int p = atomicAdd(cnt1, 1);
            amap1[p] = r;
            zn2c[p] = nm;
        }
    }
}

// ---------------- fused: softmax + compaction + margin classify + gather + norm ----------------
template <int CLASSIFY>
__global__ void __launch_bounds__(256)
softmax_step_kernel(const float* __restrict__ L, const float* __restrict__ Xi,
                    const float* __restrict__ m2,
                    const int* __restrict__ amap_in, const int* __restrict__ ncnt,
                    float* __restrict__ Z, int* __restrict__ amap_out,
                    int* __restrict__ cnt_out, float* __restrict__ zn2_out)
{
    const int r = blockIdx.x;
    if (r >= *ncnt) return;

    __shared__ float s_row[NM];
    __shared__ int   s_id[CAP];
    __shared__ float s_w[CAP];
    __shared__ float s_redf[8];
    __shared__ int   s_wcnt[8];
    __shared__ int   s_base;
    __shared__ float s_m, s_sum;
    __shared__ float r_s1, r_s2;
    __shared__ int   r_i1;

    const int tid = threadIdx.x, lane = tid & 31, w = tid >> 5;
    const int orig = amap_in[r];
    const float4* src4 = (const float4*)(L + (size_t)r * NM);

    float lm[4] = {-FLT_MAX, -FLT_MAX, -FLT_MAX, -FLT_MAX};
#pragma unroll
    for (int u = 0; u < 8; u++) {
        int i = tid + u * 256;
        float4 v = src4[i];
        ((float4*)s_row)[i] = v;
        lm[u & 3] = fmaxf(lm[u & 3], fmaxf(fmaxf(v.x, v.y), fmaxf(v.z, v.w)));
    }
    float m = fmaxf(fmaxf(lm[0], lm[1]), fmaxf(lm[2], lm[3]));
#pragma unroll
    for (int o = 16; o; o >>= 1) m = fmaxf(m, __shfl_xor_sync(0xffffffffu, m, o));
    if (lane == 0) s_redf[w] = m;
    __syncthreads();
    if (tid == 0) {
        float t = s_redf[0];
        for (int i = 1; i < 8; i++) t = fmaxf(t, s_redf[i]);
        s_m = t;
    }
    __syncthreads();
    m = s_m;

    float s = 0.f;
    for (int i = tid; i < NM; i += 256) s += __expf(s_row[i] - m);
#pragma unroll
    for (int o = 16; o; o >>= 1) s += __shfl_xor_sync(0xffffffffu, s, o);
    __syncthreads();
    if (lane == 0) s_redf[w] = s;
    __syncthreads();
    if (tid == 0) {
        float t = 0.f;
        for (int i = 0; i < 8; i++) t += s_redf[i];
        s_sum = t;
        s_base = 0;
    }
    __syncthreads();
    const float sum = s_sum;
    const float thr = m - 30.0f;

    for (int i0 = 0; i0 < NM; i0 += 256) {
        int i = i0 + tid;
        float v = s_row[i];
        bool p = (v > thr);
        unsigned mk = __ballot_sync(0xffffffffu, p);
        if (lane == 0) s_wcnt[w] = __popc(mk);
        __syncthreads();
        int woff = 0, tot = 0;
#pragma unroll
        for (int q = 0; q < 8; q++) { if (q < w) woff += s_wcnt[q]; tot += s_wcnt[q]; }
        int pos = s_base + woff + __popc(mk & ((1u << lane) - 1u));
        if (p && pos < CAP) { s_id[pos] = i; s_w[pos] = __expf(v - m) / sum; }
        __syncthreads();
        if (tid == 0) s_base = min(s_base + tot, CAP);
        __syncthreads();
    }
    const int n = s_base;

    bool conv = false;
    int sel = 0;
    if (CLASSIFY) {
        if (w == 0) {
            float s1 = -FLT_MAX, s2 = -FLT_MAX; int i1 = 0;
            for (int c = lane; c < n; c += 32) {
                float sc = (2.f * s_w[c] - 1.f) * m2[s_id[c]];
                top2_merge(s1, i1, s2, sc, s_id[c], -FLT_MAX);
            }
#pragma unroll
            for (int o = 16; o; o >>= 1) {
                float os1 = __shfl_xor_sync(0xffffffffu, s1, o);
                int   oi1 = __shfl_xor_sync(0xffffffffu, i1, o);
                float os2 = __shfl_xor_sync(0xffffffffu, s2, o);
                top2_merge(s1, i1, s2, os1, oi1, os2);
            }
            if (lane == 0) { r_s1 = s1; r_s2 = s2; r_i1 = i1; }
        }
        __syncthreads();
        conv = (n == 1) || (r_s1 > 0.f && r_s1 - r_s2 > MARGIN);
        sel = (n == 1) ? s_id[0] : r_i1;
    }

    if (CLASSIFY && conv) {
        float2 v = ((const float2*)(Xi + (size_t)sel * DD))[tid];
        ((float2*)(Z + (size_t)orig * DD))[tid] = v;
    } else {
        float2 acc = make_float2(0.f, 0.f);
        for (int c = 0; c < n; c++) {
            float wv = s_w[c];
            float2 v = ((const float2*)(Xi + (size_t)s_id[c] * DD))[tid];
            acc.x = fmaf(wv, v.x, acc.x);
            acc.y = fmaf(wv, v.y, acc.y);
        }
        ((float2*)(Z + (size_t)orig * DD))[tid] = acc;
        if (CLASSIFY) {
            float nr = acc.x * acc.x;
            nr = fmaf(acc.y, acc.y, nr);
#pragma unroll
            for (int o = 16; o; o >>= 1) nr += __shfl_xor_sync(0xffffffffu, nr, o);
            __syncthreads();
            if (lane == 0) s_redf[w] = nr;
            __syncthreads();
            if (tid == 0) {
                float nm = 0.f;
                for (int i = 0; i < 8; i++) nm += s_redf[i];
                int p = atomicAdd(cnt_out, 1);
                amap_out[p] = orig;
                zn2_out[p] = nm;
            }
        }
    }
}

// ---------------- interleave planes -> output [B, D, 5] ----------------
__global__ void interleave_kernel(const float* __restrict__ Z, float* __restrict__ out, int BD)
{
    int i = blockIdx.x * blockDim.x + threadIdx.x;
    if (i >= BD * NCOL) return;
    int j = i % NCOL;
    int bd = i / NCOL;
    out[i] = Z[(size_t)j * BD + bd];
}

// ---------------- host launcher ----------------
extern "C" void kernel_launch(void* const* d_in, const int* in_sizes, int n_in,
                              void* d_out, int out_size)
{
    const float* x  = (const float*)d_in[0];   // [2048, 512]
    const float* Xi = (const float*)d_in[1];   // [8192, 512]
    float* out = (float*)d_out;                // [2048, 512, 5]

    float *pL, *pZ, *pm2, *px2, *pzn2c, *pcw;
    int *pcidx, *pccnt, *pamap1, *pamap2, *pcnt1, *pcnt2;
    cudaGetSymbolAddress((void**)&pL,     g_L);
    cudaGetSymbolAddress((void**)&pZ,     g_Z);
    cudaGetSymbolAddress((void**)&pm2,    g_m2);
    cudaGetSymbolAddress((void**)&px2,    g_x2);
    cudaGetSymbolAddress((void**)&pzn2c,  g_zn2c);
    cudaGetSymbolAddress((void**)&pcidx,  g_cidx);
    cudaGetSymbolAddress((void**)&pcw,    g_cw);
    cudaGetSymbolAddress((void**)&pccnt,  g_ccnt);
    cudaGetSymbolAddress((void**)&pamap1, g_amap1);
    cudaGetSymbolAddress((void**)&pamap2, g_amap2);
    cudaGetSymbolAddress((void**)&pcnt1,  g_cnt1);
    cudaGetSymbolAddress((void**)&pcnt2,  g_cnt2);

    clear_kernel<<<(MR + 255) / 256, 256>>>(pamap1, pamap2, pcnt1, pcnt2);

    rownorm2_kernel<<<NM, 128>>>(Xi, pm2, DD);
    rownorm2_kernel<<<BQ, 128>>>(x,  px2, DD);

    dim3 gnt0(NM / 128, BQ / 256);
    sgemm_nt_ep<<<gnt0, 256>>>(x, Xi, px2, pm2, pL, BQ, NM, DD);

    stats_planes_kernel<<<BQ, 256>>>(pL, pcidx, pcw, pccnt);

    init_activity_kernel<<<MR, 128>>>(Xi, pm2, pcidx, pcw, pccnt, pZ, pamap1, pcnt1, pzn2c);

    dim3 gnt1(NM / 128, MR / 256);
    sgemm_nt_ep_ind<<<gnt1, 256>>>(pZ, pamap1, pcnt1, Xi, pzn2c, pm2, pL);
    softmax_step_kernel<1><<<MR, 256>>>(pL, Xi, pm2, pamap1, pcnt1, pZ, pamap2, pcnt2, pzn2c);

    sgemm_nt_ep_ind<<<gnt1, 256>>>(pZ, pamap2, pcnt2, Xi, pzn2c, pm2, pL);
    softmax_step_kernel<0><<<MR, 256>>>(pL, Xi, pm2, pamap2, pcnt2, pZ, nullptr, nullptr, nullptr);

    interleave_kernel<<<(BQ * DD * NCOL + 255) / 256, 256>>>(pZ, out, BQ * DD);
}

// round 17
// speedup vs baseline: 1.0105x; 1.0105x over previous
#include <cuda_runtime.h>
#include <math.h>
#include <float.h>
#include <stdint.h>

// Problem constants (fixed: x[2048,512], memories[8192,512], k=5, beta=1, steps=2)
#define BQ 2048
#define NM 8192
#define DD 512
#define NCOL 5
#define MR (NCOL * BQ)          // 10240 batched z rows
#define BISECT_ITERS 64
#define CAP 1024                // per-row sparse support cap
#define MARGIN 300.0f           // score-margin for provable one-hot collapse

// ---------------- scratch (device globals; no runtime allocation) ----------------
__device__ float g_L[(size_t)MR * NM];
__device__ float g_Z[(size_t)MR * DD];
__device__ int   g_cidx[(size_t)BQ * CAP];
__device__ float g_cw[(size_t)NCOL * BQ * CAP];
__device__ int   g_ccnt[BQ];
__device__ float g_m2[NM];
__device__ float g_x2[BQ];
__device__ float g_zn2c[MR];
__device__ int   g_amap1[MR];
__device__ int   g_amap2[MR];
__device__ int   g_cnt1;
__device__ int   g_cnt2;

__device__ __forceinline__ float sigmoidf_(float t) { return 1.0f / (1.0f + __expf(-t)); }

__device__ __forceinline__ void top2_merge(float& s1, int& i1, float& s2,
                                           float os1, int oi1, float os2) {
    if (os1 > s1) { s2 = fmaxf(s1, os2); s1 = os1; i1 = oi1; }
    else          { s2 = fmaxf(s2, os1); }
}

// descending compare-exchange with index tie-break
__device__ __forceinline__ void ce6(float* v, int* ix, int a, int b) {
    bool sw = (v[a] < v[b]) || (v[a] == v[b] && ix[a] > ix[b]);
    if (sw) {
        float tv = v[a]; v[a] = v[b]; v[b] = tv;
        int   ti = ix[a]; ix[a] = ix[b]; ix[b] = ti;
    }
}
__device__ __forceinline__ void sort6(float* v, int* ix) {
    ce6(v, ix, 0, 5); ce6(v, ix, 1, 3); ce6(v, ix, 2, 4);
    ce6(v, ix, 1, 2); ce6(v, ix, 3, 4);
    ce6(v, ix, 0, 3); ce6(v, ix, 2, 5);
    ce6(v, ix, 0, 1); ce6(v, ix, 2, 3); ce6(v, ix, 4, 5);
    ce6(v, ix, 1, 2); ce6(v, ix, 3, 4);
}
__device__ __forceinline__ void ins6(float val, int idx, float* v, int* ix) {
    if (val > v[5] || (val == v[5] && idx < ix[5])) {
        v[5] = val; ix[5] = idx;
#pragma unroll
        for (int j = 5; j > 0; j--) ce6(v, ix, j - 1, j);
    }
}

// ---------------- clear lists/counters ----------------
__global__ void clear_kernel(int* amap1, int* amap2, int* cnt1, int* cnt2)
{
    int i = blockIdx.x * blockDim.x + threadIdx.x;
    if (i < MR) { amap1[i] = 0; amap2[i] = 0; }
    if (i == 0) { *cnt1 = 0; *cnt2 = 0; }
}

// ---------------- row squared-norms (direct) ----------------
__global__ void rownorm2_kernel(const float* __restrict__ A, float* __restrict__ out, int cols)
{
    int r = blockIdx.x;
    const float* a = A + (size_t)r * cols;
    float s = 0.f;
    for (int c = threadIdx.x; c < cols; c += blockDim.x) { float v = a[c]; s = fmaf(v, v, s); }
#pragma unroll
    for (int o = 16; o; o >>= 1) s += __shfl_xor_sync(0xffffffffu, s, o);
    __shared__ float red[4];
    if ((threadIdx.x & 31) == 0) red[threadIdx.x >> 5] = s;
    __syncthreads();
    if (threadIdx.x == 0) out[r] = red[0] + red[1] + red[2] + red[3];
}

// ---------------- GEMM compute stage (128x128 tile, 8x8 per thread) ----------------
__device__ __forceinline__ void mm_stage(const float (*As)[128], const float (*Bs)[128],
                                         float acc[8][8], int ty, int tx)
{
#pragma unroll
    for (int kk = 0; kk < 16; kk++) {
        float a[8], b[8];
        float4 a0 = *(const float4*)&As[kk][ty * 8];
        float4 a1 = *(const float4*)&As[kk][ty * 8 + 4];
        float4 b0 = *(const float4*)&Bs[kk][tx * 8];
        float4 b1 = *(const float4*)&Bs[kk][tx * 8 + 4];
        a[0]=a0.x; a[1]=a0.y; a[2]=a0.z; a[3]=a0.w; a[4]=a1.x; a[5]=a1.y; a[6]=a1.z; a[7]=a1.w;
        b[0]=b0.x; b[1]=b0.y; b[2]=b0.z; b[3]=b0.w; b[4]=b1.x; b[5]=b1.y; b[6]=b1.z; b[7]=b1.w;
#pragma unroll
        for (int i = 0; i < 8; i++)
#pragma unroll
            for (int j = 0; j < 8; j++) acc[i][j] = fmaf(a[i], b[j], acc[i][j]);
    }
}

// Conflict-free transposed staging: each lane owns a distinct row (lrow = tid&127),
// k-half lcb = (tid>>7)*8.  STS bank = lrow mod 32 = lane -> no conflicts.
__device__ __forceinline__ void mm_storeT(float (*As)[128], float (*Bs)[128],
                                          int lrow, int lcb,
                                          float4 a0, float4 a1, float4 b0, float4 b1)
{
    As[lcb + 0][lrow] = a0.x; As[lcb + 1][lrow] = a0.y;
    As[lcb + 2][lrow] = a0.z; As[lcb + 3][lrow] = a0.w;
    As[lcb + 4][lrow] = a1.x; As[lcb + 5][lrow] = a1.y;
    As[lcb + 6][lrow] = a1.z; As[lcb + 7][lrow] = a1.w;
    Bs[lcb + 0][lrow] = b0.x; Bs[lcb + 1][lrow] = b0.y;
    Bs[lcb + 2][lrow] = b0.z; Bs[lcb + 3][lrow] = b0.w;
    Bs[lcb + 4][lrow] = b1.x; Bs[lcb + 5][lrow] = b1.y;
    Bs[lcb + 6][lrow] = b1.z; Bs[lcb + 7][lrow] = b1.w;
}

// ---------------- NT SGEMM (fp32, double-buffered) with distance epilogue, direct A ----------------
__global__ void __launch_bounds__(256, 2)
sgemm_nt_ep(const float* __restrict__ A, const float* __restrict__ Bm,
            const float* __restrict__ arow, const float* __restrict__ bcol,
            float* __restrict__ C, int M, int N, int K)
{
    __shared__ float As[2][16][128];
    __shared__ float Bs[2][16][128];
    const int bm = blockIdx.y * 128;
    const int bn = blockIdx.x * 128;
    const int tid = threadIdx.x;
    const int tx = tid & 15;
    const int ty = tid >> 4;
    const int lrow = tid & 127;
    const int lcb = (tid >> 7) * 8;

    const float* pa = A + (size_t)(bm + lrow) * K + lcb;
    const float* pb = Bm + (size_t)(bn + lrow) * K + lcb;

    float acc[8][8];
#pragma unroll
    for (int i = 0; i < 8; i++)
#pragma unroll
        for (int j = 0; j < 8; j++) acc[i][j] = 0.f;

    const int NS = K >> 4;
    float4 ra0 = *(const float4*)pa;
    float4 ra1 = *(const float4*)(pa + 4);
    float4 rb0 = *(const float4*)pb;
    float4 rb1 = *(const float4*)(pb + 4);
    mm_storeT(As[0], Bs[0], lrow, lcb, ra0, ra1, rb0, rb1);
    __syncthreads();

    for (int s = 0; s < NS; s++) {
        if (s + 1 < NS) {
            int k0 = (s + 1) << 4;
            ra0 = *(const float4*)(pa + k0);
            ra1 = *(const float4*)(pa + k0 + 4);
            rb0 = *(const float4*)(pb + k0);
            rb1 = *(const float4*)(pb + k0 + 4);
        }
        mm_stage(As[s & 1], Bs[s & 1], acc, ty, tx);
        if (s + 1 < NS) {
            mm_storeT(As[(s + 1) & 1], Bs[(s + 1) & 1], lrow, lcb, ra0, ra1, rb0, rb1);
            __syncthreads();
        }
    }

#pragma unroll
    for (int i = 0; i < 8; i++) {
        int gr = bm + ty * 8 + i;
        float ar = arow[gr];
#pragma unroll
        for (int j = 0; j < 8; j += 4) {
            int gc = bn + tx * 8 + j;
            float4 o;
            o.x = -fmaxf((ar + bcol[gc + 0]) - 2.f * acc[i][j + 0], 0.f);
            o.y = -fmaxf((ar + bcol[gc + 1]) - 2.f * acc[i][j + 1], 0.f);
            o.z = -fmaxf((ar + bcol[gc + 2]) - 2.f * acc[i][j + 2], 0.f);
            o.w = -fmaxf((ar + bcol[gc + 3]) - 2.f * acc[i][j + 3], 0.f);
            *(float4*)(C + (size_t)gr * N + gc) = o;
        }
    }
}

// ---------------- NT SGEMM, indirect A rows (double-buffered) ----------------
__global__ void __launch_bounds__(256, 2)
sgemm_nt_ep_ind(const float* __restrict__ Z, const int* __restrict__ amap,
                const int* __restrict__ ncnt, const float* __restrict__ Bm,
                const float* __restrict__ arow, const float* __restrict__ bcol,
                float* __restrict__ C)
{
    const int bm = blockIdx.y * 128;
    if (bm >= *ncnt) return;
    __shared__ float As[2][16][128];
    __shared__ float Bs[2][16][128];
    const int bn = blockIdx.x * 128;
    const int tid = threadIdx.x;
    const int tx = tid & 15;
    const int ty = tid >> 4;
    const int lrow = tid & 127;
    const int lcb = (tid >> 7) * 8;

    const float* pa = Z + (size_t)amap[bm + lrow] * DD + lcb;
    const float* pb = Bm + (size_t)(bn + lrow) * DD + lcb;

    float acc[8][8];
#pragma unroll
    for (int i = 0; i < 8; i++)
#pragma unroll
        for (int j = 0; j < 8; j++) acc[i][j] = 0.f;

    const int NS = DD >> 4;   // 32
    float4 ra0 = *(const float4*)pa;
    float4 ra1 = *(const float4*)(pa + 4);
    float4 rb0 = *(const float4*)pb;
    float4 rb1 = *(const float4*)(pb + 4);
    mm_storeT(As[0], Bs[0], lrow, lcb, ra0, ra1, rb0, rb1);
    __syncthreads();

    for (int s = 0; s < NS; s++) {
        if (s + 1 < NS) {
            int k0 = (s + 1) << 4;
            ra0 = *(const float4*)(pa + k0);
            ra1 = *(const float4*)(pa + k0 + 4);
            rb0 = *(const float4*)(pb + k0);
            rb1 = *(const float4*)(pb + k0 + 4);
        }
        mm_stage(As[s & 1], Bs[s & 1], acc, ty, tx);
        if (s + 1 < NS) {
            mm_storeT(As[(s + 1) & 1], Bs[(s + 1) & 1], lrow, lcb, ra0, ra1, rb0, rb1);
            __syncthreads();
        }
    }

#pragma unroll
    for (int i = 0; i < 8; i++) {
        int gr = bm + ty * 8 + i;
        float ar = arow[gr];
#pragma unroll
        for (int j = 0; j < 8; j += 4) {
            int gc = bn + tx * 8 + j;
            float4 o;
            o.x = -fmaxf((ar + bcol[gc + 0]) - 2.f * acc[i][j + 0], 0.f);
            o.y = -fmaxf((ar + bcol[gc + 1]) - 2.f * acc[i][j + 1], 0.f);
            o.z = -fmaxf((ar + bcol[gc + 2]) - 2.f * acc[i][j + 2], 0.f);
            o.w = -fmaxf((ar + bcol[gc + 3]) - 2.f * acc[i][j + 3], 0.f);
            *(float4*)(C + (size_t)gr * NM + gc) = o;
        }
    }
}

// ---------------- stats + LML + sparse plane extraction (one block per x-row) ----------------
__global__ void __launch_bounds__(256)
stats_planes_kernel(const float* __restrict__ X, int* __restrict__ cidx,
                    float* __restrict__ cw, int* __restrict__ ccnt)
{
    __shared__ float s_row[NM];
    __shared__ float s_cand[CAP];
    __shared__ int   s_ci[CAP];
    __shared__ float s_redf[8];
    __shared__ float s_t6v[8][6];
    __shared__ int   s_t6i[8][6];
    __shared__ float s_topv[6];
    __shared__ int   s_wcnt[8];
    __shared__ int   s_base;
    __shared__ float s_max, s_sum;
    __shared__ float s_nu[4];

    const int b = blockIdx.x;
    const int tid = threadIdx.x, lane = tid & 31, w = tid >> 5;
    const float4* x4 = (const float4*)(X + (size_t)b * NM);

    float lm[4] = {-FLT_MAX, -FLT_MAX, -FLT_MAX, -FLT_MAX};
#pragma unroll
    for (int u = 0; u < 8; u++) {
        int i = tid + u * 256;
        float4 v = x4[i];
        ((float4*)s_row)[i] = v;
        lm[u & 3] = fmaxf(lm[u & 3], fmaxf(fmaxf(v.x, v.y), fmaxf(v.z, v.w)));
    }
    float lmax = fmaxf(fmaxf(lm[0], lm[1]), fmaxf(lm[2], lm[3]));
#pragma unroll
    for (int o = 16; o; o >>= 1) lmax = fmaxf(lmax, __shfl_xor_sync(0xffffffffu, lmax, o));
    if (lane == 0) s_redf[w] = lmax;
    __syncthreads();
    if (tid == 0) {
        float m = s_redf[0];
        for (int i = 1; i < 8; i++) m = fmaxf(m, s_redf[i]);
        s_max = m;
    }
    __syncthreads();
    const float rmax = s_max;

    float ls = 0.f;
    for (int i = tid; i < NM; i += 256) ls += __expf(s_row[i] - rmax);
#pragma unroll
    for (int o = 16; o; o >>= 1) ls += __shfl_xor_sync(0xffffffffu, ls, o);
    __syncthreads();
    if (lane == 0) s_redf[w] = ls;
    __syncthreads();
    if (tid == 0) {
        float t = 0.f;
        for (int i = 0; i < 8; i++) t += s_redf[i];
        s_sum = t;
    }

    // single-pass top-6
    float tv[6]; int ti[6];
#pragma unroll
    for (int j = 0; j < 6; j++) { tv[j] = -FLT_MAX; ti[j] = 0x7fffffff; }
    for (int i = tid; i < NM; i += 256) ins6(s_row[i], i, tv, ti);
#pragma unroll
    for (int o = 16; o; o >>= 1) {
        float ov[6]; int oi[6];
#pragma unroll
        for (int j = 0; j < 6; j++) {
            ov[j] = __shfl_xor_sync(0xffffffffu, tv[j], o);
            oi[j] = __shfl_xor_sync(0xffffffffu, ti[j], o);
        }
        float nv[6]; int ni[6];
#pragma unroll
        for (int q = 0; q < 6; q++) {
            bool ta = (tv[q] > ov[5 - q]) || (tv[q] == ov[5 - q] && ti[q] <= oi[5 - q]);
            nv[q] = ta ? tv[q] : ov[5 - q];
            ni[q] = ta ? ti[q] : oi[5 - q];
        }
#pragma unroll
        for (int j = 0; j < 6; j++) { tv[j] = nv[j]; ti[j] = ni[j]; }
        sort6(tv, ti);
    }
    if (lane == 0) {
#pragma unroll
        for (int j = 0; j < 6; j++) { s_t6v[w][j] = tv[j]; s_t6i[w][j] = ti[j]; }
    }
    __syncthreads();
    if (tid == 0) {
        float fv[6]; int fi[6];
#pragma unroll
        for (int j = 0; j < 6; j++) { fv[j] = s_t6v[0][j]; fi[j] = s_t6i[0][j]; }
        for (int q = 1; q < 8; q++)
            for (int j = 0; j < 6; j++) ins6(s_t6v[q][j], s_t6i[q][j], fv, fi);
#pragma unroll
        for (int j = 0; j < 6; j++) s_topv[j] = fv[j];
        s_base = 0;
    }
    __syncthreads();

    const float thr = s_topv[5] - 34.0f;
    for (int i0 = 0; i0 < NM; i0 += 256) {
        int i = i0 + tid;
        float v = s_row[i];
        bool p = (v > thr);
        unsigned mk = __ballot_sync(0xffffffffu, p);
        if (lane == 0) s_wcnt[w] = __popc(mk);
        __syncthreads();
        int woff = 0, tot = 0;
#pragma unroll
        for (int q = 0; q < 8; q++) { if (q < w) woff += s_wcnt[q]; tot += s_wcnt[q]; }
        int pos = s_base + woff + __popc(mk & ((1u << lane) - 1u));
        if (p && pos < CAP) { s_cand[pos] = v; s_ci[pos] = i; }
        __syncthreads();
        if (tid == 0) s_base = min(s_base + tot, CAP);
        __syncthreads();
    }
    const int total = s_base;

    if (w < 4) {
        const int kk = w + 2;
        float lo = -s_topv[kk - 1] - 7.0f;
        float hi = -s_topv[kk] + 7.0f;
        for (int it = 0; it < BISECT_ITERS; it++) {
            float mid = 0.5f * (lo + hi);
            float s = 0.f;
            for (int c = lane; c < total; c += 32) s += sigmoidf_(s_cand[c] + mid);
#pragma unroll
            for (int o = 16; o; o >>= 1) s += __shfl_xor_sync(0xffffffffu, s, o);
            if (s - (float)kk < 0.f) lo = mid; else hi = mid;
        }
        if (lane == 0) s_nu[kk - 2] = 0.5f * (lo + hi);
    }
    __syncthreads();

    const float ssum = s_sum;
    const float nu2 = s_nu[0], nu3 = s_nu[1], nu4 = s_nu[2], nu5 = s_nu[3];
    const size_t PL = (size_t)BQ * CAP;
    for (int c = tid; c < total; c += 256) {
        float xv = s_cand[c];
        float p  = __expf(xv - rmax) / ssum;
        float y2 = sigmoidf_(xv + nu2);
        float y3 = sigmoidf_(xv + nu3);
        float y4 = sigmoidf_(xv + nu4);
        float y5 = sigmoidf_(xv + nu5);
        size_t o = (size_t)b * CAP + c;
        cidx[o] = s_ci[c];
        cw[o]          = p;
        cw[PL + o]     = y2 - p;
        cw[2 * PL + o] = y3 - y2;
        cw[3 * PL + o] = y4 - y3;
        cw[4 * PL + o] = y5 - y4;
    }
    if (tid == 0) ccnt[b] = total;
}

// ---------------- init activity: margin-converged rows skip hopfield; norm fused ----------------
__global__ void __launch_bounds__(128)
init_activity_kernel(const float* __restrict__ Xi, const float* __restrict__ m2,
                     const int* __restrict__ cidx, const float* __restrict__ cw,
                     const int* __restrict__ ccnt, float* __restrict__ Z,
                     int* __restrict__ amap1, int* __restrict__ cnt1,
                     float* __restrict__ zn2c)
{
    __shared__ float s_s1[4], s_s2[4];
    __shared__ int   s_i1[4];
    __shared__ float r_s1, r_s2;
    __shared__ int   r_i1;
    __shared__ float s_nred[4];

    const int r = blockIdx.x;
    const int k = r >> 11, b = r & 2047;
    const int n = ccnt[b];
    const int* id = cidx + (size_t)b * CAP;
    const float* wp = cw + (size_t)k * ((size_t)BQ * CAP) + (size_t)b * CAP;
    const int t = threadIdx.x, lane = t & 31, w = t >> 5;

    float s1 = -FLT_MAX, s2 = -FLT_MAX; int i1 = 0;
    for (int c = t; c < n; c += 128) {
        float sc = (2.f * wp[c] - 1.f) * m2[id[c]];
        top2_merge(s1, i1, s2, sc, id[c], -FLT_MAX);
    }
#pragma unroll
    for (int o = 16; o; o >>= 1) {
        float os1 = __shfl_xor_sync(0xffffffffu, s1, o);
        int   oi1 = __shfl_xor_sync(0xffffffffu, i1, o);
        float os2 = __shfl_xor_sync(0xffffffffu, s2, o);
        top2_merge(s1, i1, s2, os1, oi1, os2);
    }
    if (lane == 0) { s_s1[w] = s1; s_i1[w] = i1; s_s2[w] = s2; }
    __syncthreads();
    if (t == 0) {
        float a1 = s_s1[0], a2 = s_s2[0]; int ai = s_i1[0];
        for (int i = 1; i < 4; i++) top2_merge(a1, ai, a2, s_s1[i], s_i1[i], s_s2[i]);
        r_s1 = a1; r_s2 = a2; r_i1 = ai;
    }
    __syncthreads();

    if (r_s1 > 0.f && r_s1 - r_s2 > MARGIN) {
        float4 v = ((const float4*)(Xi + (size_t)r_i1 * DD))[t];
        ((float4*)(Z + (size_t)r * DD))[t] = v;
    } else {
        float4 acc = make_float4(0.f, 0.f, 0.f, 0.f);
        for (int c = 0; c < n; c++) {
            float wv = wp[c];
            float4 v = ((const float4*)(Xi + (size_t)id[c] * DD))[t];
            acc.x = fmaf(wv, v.x, acc.x); acc.y = fmaf(wv, v.y, acc.y);
            acc.z = fmaf(wv, v.z, acc.z); acc.w = fmaf(wv, v.w, acc.w);
        }
        ((float4*)(Z + (size_t)r * DD))[t] = acc;
        float nr = acc.x * acc.x;
        nr = fmaf(acc.y, acc.y, nr);
        nr = fmaf(acc.z, acc.z, nr);
        nr = fmaf(acc.w, acc.w, nr);
#pragma unroll
        for (int o = 16; o; o >>= 1) nr += __shfl_xor_sync(0xffffffffu, nr, o);
        if (lane == 0) s_nred[w] = nr;
        __syncthreads();
        if (t == 0) {
            float nm = s_nred[0] + s_nred[1] + s_nred[2] + s_nred[3];
            int p = atomicAdd(cnt1, 1);
            amap1[p] = r;
            zn2c[p] = nm;
        }
    }
}

// ---------------- fused: softmax + compaction + margin classify + gather + norm ----------------
template <int CLASSIFY>
__global__ void __launch_bounds__(256)
softmax_step_kernel(const float* __restrict__ L, const float* __restrict__ Xi,
                    const float* __restrict__ m2,
                    const int* __restrict__ amap_in, const int* __restrict__ ncnt,
                    float* __restrict__ Z, int* __restrict__ amap_out,
                    int* __restrict__ cnt_out, float* __restrict__ zn2_out)
{
    const int r = blockIdx.x;
    if (r >= *ncnt) return;

    __shared__ float s_row[NM];
    __shared__ int   s_id[CAP];
    __shared__ float s_w[CAP];
    __shared__ float s_redf[8];
    __shared__ int   s_wcnt[8];
    __shared__ int   s_base;
    __shared__ float s_m, s_sum;
    __shared__ float r_s1, r_s2;
    __shared__ int   r_i1;

    const int tid = threadIdx.x, lane = tid & 31, w = tid >> 5;
    const int orig = amap_in[r];
    const float4* src4 = (const float4*)(L + (size_t)r * NM);

    float lm[4] = {-FLT_MAX, -FLT_MAX, -FLT_MAX, -FLT_MAX};
#pragma unroll
    for (int u = 0; u < 8; u++) {
        int i = tid + u * 256;
        float4 v = src4[i];
        ((float4*)s_row)[i] = v;
        lm[u & 3] = fmaxf(lm[u & 3], fmaxf(fmaxf(v.x, v.y), fmaxf(v.z, v.w)));
    }
    float m = fmaxf(fmaxf(lm[0], lm[1]), fmaxf(lm[2], lm[3]));
#pragma unroll
    for (int o = 16; o; o >>= 1) m = fmaxf(m, __shfl_xor_sync(0xffffffffu, m, o));
    if (lane == 0) s_redf[w] = m;
    __syncthreads();
    if (tid == 0) {
        float t = s_redf[0];
        for (int i = 1; i < 8; i++) t = fmaxf(t, s_redf[i]);
        s_m = t;
    }
    __syncthreads();
    m = s_m;

    float s = 0.f;
    for (int i = tid; i < NM; i += 256) s += __expf(s_row[i] - m);
#pragma unroll
    for (int o = 16; o; o >>= 1) s += __shfl_xor_sync(0xffffffffu, s, o);
    __syncthreads();
    if (lane == 0) s_redf[w] = s;
    __syncthreads();
    if (tid == 0) {
        float t = 0.f;
        for (int i = 0; i < 8; i++) t += s_redf[i];
        s_sum = t;
        s_base = 0;
    }
    __syncthreads();
    const float sum = s_sum;
    const float thr = m - 30.0f;

    for (int i0 = 0; i0 < NM; i0 += 256) {
        int i = i0 + tid;
        float v = s_row[i];
        bool p = (v > thr);
        unsigned mk = __ballot_sync(0xffffffffu, p);
        if (lane == 0) s_wcnt[w] = __popc(mk);
        __syncthreads();
        int woff = 0, tot = 0;
#pragma unroll
        for (int q = 0; q < 8; q++) { if (q < w) woff += s_wcnt[q]; tot += s_wcnt[q]; }
        int pos = s_base + woff + __popc(mk & ((1u << lane) - 1u));
        if (p && pos < CAP) { s_id[pos] = i; s_w[pos] = __expf(v - m) / sum; }
        __syncthreads();
        if (tid == 0) s_base = min(s_base + tot, CAP);
        __syncthreads();
    }
    const int n = s_base;

    bool conv = false;
    int sel = 0;
    if (CLASSIFY) {
        if (w == 0) {
            float s1 = -FLT_MAX, s2 = -FLT_MAX; int i1 = 0;
            for (int c = lane; c < n; c += 32) {
                float sc = (2.f * s_w[c] - 1.f) * m2[s_id[c]];
                top2_merge(s1, i1, s2, sc, s_id[c], -FLT_MAX);
            }
#pragma unroll
            for (int o = 16; o; o >>= 1) {
                float os1 = __shfl_xor_sync(0xffffffffu, s1, o);
                int   oi1 = __shfl_xor_sync(0xffffffffu, i1, o);
                float os2 = __shfl_xor_sync(0xffffffffu, s2, o);
                top2_merge(s1, i1, s2, os1, oi1, os2);
            }
            if (lane == 0) { r_s1 = s1; r_s2 = s2; r_i1 = i1; }
        }
        __syncthreads();
        conv = (n == 1) || (r_s1 > 0.f && r_s1 - r_s2 > MARGIN);
        sel = (n == 1) ? s_id[0] : r_i1;
    }

    if (CLASSIFY && conv) {
        float2 v = ((const float2*)(Xi + (size_t)sel * DD))[tid];
        ((float2*)(Z + (size_t)orig * DD))[tid] = v;
    } else {
        float2 acc = make_float2(0.f, 0.f);
        for (int c = 0; c < n; c++) {
            float wv = s_w[c];
            float2 v = ((const float2*)(Xi + (size_t)s_id[c] * DD))[tid];
            acc.x = fmaf(wv, v.x, acc.x);
            acc.y = fmaf(wv, v.y, acc.y);
        }
        ((float2*)(Z + (size_t)orig * DD))[tid] = acc;
        if (CLASSIFY) {
            float nr = acc.x * acc.x;
            nr = fmaf(acc.y, acc.y, nr);
#pragma unroll
            for (int o = 16; o; o >>= 1) nr += __shfl_xor_sync(0xffffffffu, nr, o);
            __syncthreads();
            if (lane == 0) s_redf[w] = nr;
            __syncthreads();
            if (tid == 0) {
                float nm = 0.f;
                for (int i = 0; i < 8; i++) nm += s_redf[i];
                int p = atomicAdd(cnt_out, 1);
                amap_out[p] = orig;
                zn2_out[p] = nm;
            }
        }
    }
}

// ---------------- interleave planes -> output [B, D, 5] ----------------
__global__ void interleave_kernel(const float* __restrict__ Z, float* __restrict__ out, int BD)
{
    int i = blockIdx.x * blockDim.x + threadIdx.x;
    if (i >= BD * NCOL) return;
    int j = i % NCOL;
    int bd = i / NCOL;
    out[i] = Z[(size_t)j * BD + bd];
}

// ---------------- host launcher ----------------
extern "C" void kernel_launch(void* const* d_in, const int* in_sizes, int n_in,
                              void* d_out, int out_size)
{
    const float* x  = (const float*)d_in[0];   // [2048, 512]
    const float* Xi = (const float*)d_in[1];   // [8192, 512]
    float* out = (float*)d_out;                // [2048, 512, 5]

    float *pL, *pZ, *pm2, *px2, *pzn2c, *pcw;
    int *pcidx, *pccnt, *pamap1, *pamap2, *pcnt1, *pcnt2;
    cudaGetSymbolAddress((void**)&pL,     g_L);
    cudaGetSymbolAddress((void**)&pZ,     g_Z);
    cudaGetSymbolAddress((void**)&pm2,    g_m2);
    cudaGetSymbolAddress((void**)&px2,    g_x2);
    cudaGetSymbolAddress((void**)&pzn2c,  g_zn2c);
    cudaGetSymbolAddress((void**)&pcidx,  g_cidx);
    cudaGetSymbolAddress((void**)&pcw,    g_cw);
    cudaGetSymbolAddress((void**)&pccnt,  g_ccnt);
    cudaGetSymbolAddress((void**)&pamap1, g_amap1);
    cudaGetSymbolAddress((void**)&pamap2, g_amap2);
    cudaGetSymbolAddress((void**)&pcnt1,  g_cnt1);
    cudaGetSymbolAddress((void**)&pcnt2,  g_cnt2);

    clear_kernel<<<(MR + 255) / 256, 256>>>(pamap1, pamap2, pcnt1, pcnt2);

    rownorm2_kernel<<<NM, 128>>>(Xi, pm2, DD);
    rownorm2_kernel<<<BQ, 128>>>(x,  px2, DD);

    dim3 gnt0(NM / 128, BQ / 128);
    sgemm_nt_ep<<<gnt0, 256>>>(x, Xi, px2, pm2, pL, BQ, NM, DD);

    stats_planes_kernel<<<BQ, 256>>>(pL, pcidx, pcw, pccnt);

    init_activity_kernel<<<MR, 128>>>(Xi, pm2, pcidx, pcw, pccnt, pZ, pamap1, pcnt1, pzn2c);

    dim3 gnt1(NM / 128, MR / 128);
    sgemm_nt_ep_ind<<<gnt1, 256>>>(pZ, pamap1, pcnt1, Xi, pzn2c, pm2, pL);
    softmax_step_kernel<1><<<MR, 256>>>(pL, Xi, pm2, pamap1, pcnt1, pZ, pamap2, pcnt2, pzn2c);

    sgemm_nt_ep_ind<<<gnt1, 256>>>(pZ, pamap2, pcnt2, Xi, pzn2c, pm2, pL);
    softmax_step_kernel<0><<<MR, 256>>>(pL, Xi, pm2, pamap2, pcnt2, pZ, nullptr, nullptr, nullptr);

    interleave_kernel<<<(BQ * DD * NCOL + 255) / 256, 256>>>(pZ, out, BQ * DD);
}